// round 2
// baseline (speedup 1.0000x reference)
#include <cuda_runtime.h>

// Problem constants
#define NPX      65536      // 16 * 64 * 64 pixels
#define KCODES   1024
#define DDIM     256
#define HW       4096       // 64*64
#define TILE_PX  128
#define TILE_K   64
#define NKT      (KCODES / TILE_K)   // 16
#define ZQ_ELEMS 16777216   // 16*256*64*64

// Scratch (device globals; allocation-free per harness rules)
__device__ float g_esq[KCODES];
__device__ float g_loss_acc;

// smem layout (floats):
//   z_s   [256][128]            32768
//   e_s   [64][257]             16448   (257 pad -> conflict-free compute reads)
//   zsq_s [128]                   128
//   s_idx [128] (as int)          128
//   swsum [8]                       8
#define ZS_F   32768
#define ES_F   (64 * 257)
#define SMEM_FLOATS (ZS_F + ES_F + 128 + 128 + 8)

// ---------------------------------------------------------------------------
// Prep: esq[k] = sequential fp32 sum of e_c^2 (mul then add, XLA-CPU order);
// zero loss accumulator.
// ---------------------------------------------------------------------------
__global__ void vq_prep(const float* __restrict__ cb) {
    int k = blockIdx.x * blockDim.x + threadIdx.x;
    if (k == 0) g_loss_acc = 0.0f;
    if (k < KCODES) {
        const float* row = cb + (size_t)k * DDIM;
        float s = 0.0f;
        for (int c = 0; c < DDIM; c++) {
            float v = row[c];
            s = __fadd_rn(s, __fmul_rn(v, v));   // sequential, no FMA contraction
        }
        g_esq[k] = s;
    }
}

// ---------------------------------------------------------------------------
// Main: fused distance-GEMM + argmin + z_q gather/write + loss partial
// ---------------------------------------------------------------------------
__global__ __launch_bounds__(256, 1)
void vq_main(const float* __restrict__ z, const float* __restrict__ cb,
             float* __restrict__ out_zq, float* __restrict__ out_idx) {
    extern __shared__ float smem[];
    float* z_s   = smem;
    float* e_s   = smem + ZS_F;
    float* zsq_s = smem + ZS_F + ES_F;
    int*   s_idx = (int*)(smem + ZS_F + ES_F + 128);
    float* swsum = smem + ZS_F + ES_F + 256;

    const int t  = threadIdx.x;
    const int tx = t & 15;        // code-group lane
    const int ty = t >> 4;        // pixel-group lane
    const int tile = blockIdx.x;  // 0..511
    const int b   = tile >> 5;           // batch index
    const int hw0 = (tile & 31) << 7;    // hw offset (contiguous 128 pixels)

    const float* zb = z + (size_t)b * (DDIM * HW) + hw0;

    // Load z tile [256 c][128 px] into smem (fully coalesced: hw is fast axis)
    #pragma unroll
    for (int r = 0; r < 32; r++) {
        int e  = r * 256 + t;     // float4 task id, 8192 total
        int c  = e >> 5;
        int f4 = e & 31;
        float4 v = ((const float4*)(zb + (size_t)c * HW))[f4];
        *((float4*)&z_s[c * TILE_PX + f4 * 4]) = v;
    }
    __syncthreads();

    // Per-pixel zsq: sequential fp32 sum of z_c^2 (mul then add, XLA-CPU order)
    if (t < TILE_PX) {
        float s = 0.0f;
        for (int c = 0; c < DDIM; c++) {
            float v = z_s[c * TILE_PX + t];
            s = __fadd_rn(s, __fmul_rn(v, v));
        }
        zsq_s[t] = s;
    }

    float bestd[8];
    int   bestk[8];
    #pragma unroll
    for (int i = 0; i < 8; i++) { bestd[i] = 3.4e38f; bestk[i] = 0; }

    for (int kt = 0; kt < NKT; kt++) {
        __syncthreads();
        // Load codebook tile [64 k][256 c] -> e_s[k*257 + c]
        const float* cbt = cb + (size_t)kt * TILE_K * DDIM;
        #pragma unroll
        for (int i = 0; i < 16; i++) {
            int e  = i * 256 + t;     // 4096 float4 tasks
            int k  = e >> 6;
            int c4 = e & 63;
            float4 v = ((const float4*)(cbt + k * DDIM))[c4];
            float* dst = &e_s[k * 257 + c4 * 4];
            dst[0] = v.x; dst[1] = v.y; dst[2] = v.z; dst[3] = v.w;
        }
        __syncthreads();

        float acc[8][4];
        #pragma unroll
        for (int i = 0; i < 8; i++)
            #pragma unroll
            for (int j = 0; j < 4; j++) acc[i][j] = 0.0f;

        // dot products: 8 px x 4 codes per thread.
        // Single accumulator per element, ascending c, fused FMA ->
        // bit-identical to Eigen gebp's per-element accumulation.
        #pragma unroll 8
        for (int c = 0; c < DDIM; c++) {
            float4 za  = *((const float4*)&z_s[c * TILE_PX + ty * 8]);
            float4 zb4 = *((const float4*)&z_s[c * TILE_PX + ty * 8 + 4]);
            float rz0 = za.x, rz1 = za.y, rz2 = za.z, rz3 = za.w;
            float rz4 = zb4.x, rz5 = zb4.y, rz6 = zb4.z, rz7 = zb4.w;
            float re[4];
            #pragma unroll
            for (int j = 0; j < 4; j++)
                re[j] = e_s[(tx + 16 * j) * 257 + c];   // conflict-free
            #pragma unroll
            for (int j = 0; j < 4; j++) {
                acc[0][j] = fmaf(rz0, re[j], acc[0][j]);
                acc[1][j] = fmaf(rz1, re[j], acc[1][j]);
                acc[2][j] = fmaf(rz2, re[j], acc[2][j]);
                acc[3][j] = fmaf(rz3, re[j], acc[3][j]);
                acc[4][j] = fmaf(rz4, re[j], acc[4][j]);
                acc[5][j] = fmaf(rz5, re[j], acc[5][j]);
                acc[6][j] = fmaf(rz6, re[j], acc[6][j]);
                acc[7][j] = fmaf(rz7, re[j], acc[7][j]);
            }
        }

        // d = fl( fl(zsq + esq_k) - fl(2*dot) )   -- exact reference rounding
        #pragma unroll
        for (int j = 0; j < 4; j++) {
            int kg = kt * TILE_K + tx + 16 * j;
            float eq = __ldg(&g_esq[kg]);
            #pragma unroll
            for (int i = 0; i < 8; i++) {
                float t1 = __fadd_rn(zsq_s[ty * 8 + i], eq);
                float d  = __fsub_rn(t1, __fmul_rn(2.0f, acc[i][j]));
                if (d < bestd[i]) { bestd[i] = d; bestk[i] = kg; }
            }
        }
    }

    // Half-warp (16-lane) butterfly min-reduce with lowest-index tie-break
    #pragma unroll
    for (int i = 0; i < 8; i++) {
        float d = bestd[i];
        int   k = bestk[i];
        #pragma unroll
        for (int off = 8; off >= 1; off >>= 1) {
            float od = __shfl_xor_sync(0xFFFFFFFFu, d, off);
            int   ok = __shfl_xor_sync(0xFFFFFFFFu, k, off);
            if (od < d || (od == d && ok < k)) { d = od; k = ok; }
        }
        if (tx == 0) s_idx[ty * 8 + i] = k;
    }
    __syncthreads();

    // Epilogue: straight-through z_q write (coalesced), loss partial, idx write
    float lsum = 0.0f;
    float* out_base = out_zq + (size_t)b * (DDIM * HW) + hw0;
    #pragma unroll 4
    for (int r = 0; r < 128; r++) {
        int e  = r * 256 + t;       // 32768 elements
        int c  = e >> 7;
        int px = e & 127;
        int kk = s_idx[px];
        float q  = __ldg(&cb[(size_t)kk * DDIM + c]);
        float zv = z_s[c * TILE_PX + px];
        float dd = __fsub_rn(q, zv);                 // z_q - z
        lsum = fmaf(dd, dd, lsum);                   // loss partial
        out_base[(size_t)c * HW + px] = __fadd_rn(zv, dd);  // z + (z_q - z)
    }
    if (t < 128) out_idx[(size_t)tile * TILE_PX + t] = (float)s_idx[t];

    // block loss reduce
    #pragma unroll
    for (int off = 16; off >= 1; off >>= 1)
        lsum += __shfl_xor_sync(0xFFFFFFFFu, lsum, off);
    if ((t & 31) == 0) swsum[t >> 5] = lsum;
    __syncthreads();
    if (t == 0) {
        float bs = 0.0f;
        #pragma unroll
        for (int w = 0; w < 8; w++) bs += swsum[w];
        atomicAdd(&g_loss_acc, bs);
    }
}

// ---------------------------------------------------------------------------
// Finalize: loss = mean + BETA*mean = 1.25 * (sum / 2^24)
// ---------------------------------------------------------------------------
__global__ void vq_finalize(float* __restrict__ out) {
    float m = __fmul_rn(g_loss_acc, 1.0f / (float)ZQ_ELEMS);  // /2^24 exact
    out[ZQ_ELEMS + NPX] = __fmul_rn(1.25f, m);
}

extern "C" void kernel_launch(void* const* d_in, const int* in_sizes, int n_in,
                              void* d_out, int out_size) {
    const float* z  = (const float*)d_in[0];
    const float* cb = (const float*)d_in[1];
    float* out = (float*)d_out;

    // out layout: [z_q: 16777216][idx: 65536][loss: 1]
    float* out_zq  = out;
    float* out_idx = out + ZQ_ELEMS;

    vq_prep<<<4, 256>>>(cb);

    size_t smem_bytes = SMEM_FLOATS * sizeof(float);
    cudaFuncSetAttribute(vq_main, cudaFuncAttributeMaxDynamicSharedMemorySize,
                         (int)smem_bytes);
    vq_main<<<NPX / TILE_PX, 256, smem_bytes>>>(z, cb, out_zq, out_idx);

    vq_finalize<<<1, 1>>>(out);
}

// round 3
// speedup vs baseline: 1.0595x; 1.0595x over previous
#include <cuda_runtime.h>

// Problem constants
#define NPX      65536      // 16 * 64 * 64 pixels
#define KCODES   1024
#define DDIM     256
#define HW       4096       // 64*64
#define TILE_PX  128
#define TILE_K   64
#define NKT      (KCODES / TILE_K)   // 16
#define ZQ_ELEMS 16777216   // 16*256*64*64

// Scratch (device globals; allocation-free per harness rules)
__device__ float g_esq[KCODES];
__device__ float g_loss_acc;

// smem layout (floats):
//   z_s   [256][128]            32768
//   e_s   [64][257]             16448   (257 pad -> conflict-free compute reads)
//   zsq_s [128]                   128
//   s_idx [128] (as int)          128
//   swsum [8]                       8
#define ZS_F   32768
#define ES_F   (64 * 257)
#define SMEM_FLOATS (ZS_F + ES_F + 128 + 128 + 8)

// Packed fp32x2 FMA (Blackwell FFMA2): each half is IEEE fp32 fma.rn ->
// bit-identical to two independent fmaf() calls.
#define FMA_F32X2(d, a, b, c_) \
    asm("fma.rn.f32x2 %0, %1, %2, %3;" : "=l"(d) : "l"(a), "l"(b), "l"(c_))
#define PACK2(out, lo, hi) \
    asm("mov.b64 %0, {%1, %2};" : "=l"(out) : "r"(lo), "r"(hi))
#define UNPACK2(lo, hi, in) \
    asm("mov.b64 {%0, %1}, %2;" : "=r"(lo), "=r"(hi) : "l"(in))

// ---------------------------------------------------------------------------
// Prep: esq[k] = sequential fp32 sum of e_c^2 (mul then add); zero loss acc.
// ---------------------------------------------------------------------------
__global__ void vq_prep(const float* __restrict__ cb) {
    int k = blockIdx.x * blockDim.x + threadIdx.x;
    if (k == 0) g_loss_acc = 0.0f;
    if (k < KCODES) {
        const float* row = cb + (size_t)k * DDIM;
        float s = 0.0f;
        #pragma unroll 8
        for (int c = 0; c < DDIM; c++) {
            float v = row[c];
            s = __fadd_rn(s, __fmul_rn(v, v));   // sequential, no FMA contraction
        }
        g_esq[k] = s;
    }
}

// ---------------------------------------------------------------------------
// Main: fused distance-GEMM (FFMA2) + argmin + z_q gather/write + loss partial
// ---------------------------------------------------------------------------
__global__ __launch_bounds__(256, 1)
void vq_main(const float* __restrict__ z, const float* __restrict__ cb,
             float* __restrict__ out_zq, float* __restrict__ out_idx) {
    extern __shared__ float smem[];
    float* z_s   = smem;
    float* e_s   = smem + ZS_F;
    float* zsq_s = smem + ZS_F + ES_F;
    int*   s_idx = (int*)(smem + ZS_F + ES_F + 128);
    float* swsum = smem + ZS_F + ES_F + 256;

    const int t  = threadIdx.x;
    const int tx = t & 15;        // code-group lane
    const int ty = t >> 4;        // pixel-group lane
    const int tile = blockIdx.x;  // 0..511
    const int b   = tile >> 5;           // batch index
    const int hw0 = (tile & 31) << 7;    // hw offset (contiguous 128 pixels)

    const float* zb = z + (size_t)b * (DDIM * HW) + hw0;

    // Load z tile [256 c][128 px] into smem (fully coalesced: hw is fast axis)
    #pragma unroll
    for (int r = 0; r < 32; r++) {
        int e  = r * 256 + t;     // float4 task id, 8192 total
        int c  = e >> 5;
        int f4 = e & 31;
        float4 v = ((const float4*)(zb + (size_t)c * HW))[f4];
        *((float4*)&z_s[c * TILE_PX + f4 * 4]) = v;
    }
    __syncthreads();

    // Per-pixel zsq: sequential fp32 sum of z_c^2 (mul then add)
    if (t < TILE_PX) {
        float s = 0.0f;
        for (int c = 0; c < DDIM; c++) {
            float v = z_s[c * TILE_PX + t];
            s = __fadd_rn(s, __fmul_rn(v, v));
        }
        zsq_s[t] = s;
    }

    float bestd[8];
    int   bestk[8];
    #pragma unroll
    for (int i = 0; i < 8; i++) { bestd[i] = 3.4e38f; bestk[i] = 0; }

    for (int kt = 0; kt < NKT; kt++) {
        __syncthreads();
        // Load codebook tile [64 k][256 c] -> e_s[k*257 + c]
        const float* cbt = cb + (size_t)kt * TILE_K * DDIM;
        #pragma unroll
        for (int i = 0; i < 16; i++) {
            int e  = i * 256 + t;     // 4096 float4 tasks
            int k  = e >> 6;
            int c4 = e & 63;
            float4 v = ((const float4*)(cbt + k * DDIM))[c4];
            float* dst = &e_s[k * 257 + c4 * 4];
            dst[0] = v.x; dst[1] = v.y; dst[2] = v.z; dst[3] = v.w;
        }
        __syncthreads();

        // acc2[u][j]: pixel-pair (ty*8+2u, ty*8+2u+1) x code (tx+16j).
        // Each 64-bit accumulator holds two independent fp32 chains ->
        // bit-identical to the scalar sequential fmaf chain.
        unsigned long long acc2[4][4];
        #pragma unroll
        for (int u = 0; u < 4; u++)
            #pragma unroll
            for (int j = 0; j < 4; j++) acc2[u][j] = 0ULL;

        #pragma unroll 8
        for (int c = 0; c < DDIM; c++) {
            // z pixel pairs: adjacent floats -> direct LDS.64, no packing movs
            unsigned long long zp[4];
            #pragma unroll
            for (int u = 0; u < 4; u++)
                zp[u] = *((const unsigned long long*)&z_s[c * TILE_PX + ty * 8 + 2 * u]);
            // e broadcast pairs (conflict-free reads: bank = tx+16j+c mod 32)
            unsigned long long reb[4];
            #pragma unroll
            for (int j = 0; j < 4; j++) {
                float re = e_s[(tx + 16 * j) * 257 + c];
                unsigned int ri = __float_as_uint(re);
                PACK2(reb[j], ri, ri);
            }
            #pragma unroll
            for (int u = 0; u < 4; u++)
                #pragma unroll
                for (int j = 0; j < 4; j++)
                    FMA_F32X2(acc2[u][j], zp[u], reb[j], acc2[u][j]);
        }

        // d = fl( fl(zsq + esq_k) - fl(2*dot) )   -- exact reference rounding
        #pragma unroll
        for (int j = 0; j < 4; j++) {
            int kg = kt * TILE_K + tx + 16 * j;
            float eq = __ldg(&g_esq[kg]);
            #pragma unroll
            for (int u = 0; u < 4; u++) {
                unsigned int lo, hi;
                UNPACK2(lo, hi, acc2[u][j]);
                float d0 = __fsub_rn(__fadd_rn(zsq_s[ty * 8 + 2 * u], eq),
                                     __fmul_rn(2.0f, __uint_as_float(lo)));
                float d1 = __fsub_rn(__fadd_rn(zsq_s[ty * 8 + 2 * u + 1], eq),
                                     __fmul_rn(2.0f, __uint_as_float(hi)));
                if (d0 < bestd[2 * u])     { bestd[2 * u] = d0;     bestk[2 * u] = kg; }
                if (d1 < bestd[2 * u + 1]) { bestd[2 * u + 1] = d1; bestk[2 * u + 1] = kg; }
            }
        }
    }

    // Half-warp (16-lane) butterfly min-reduce with lowest-index tie-break
    #pragma unroll
    for (int i = 0; i < 8; i++) {
        float d = bestd[i];
        int   k = bestk[i];
        #pragma unroll
        for (int off = 8; off >= 1; off >>= 1) {
            float od = __shfl_xor_sync(0xFFFFFFFFu, d, off);
            int   ok = __shfl_xor_sync(0xFFFFFFFFu, k, off);
            if (od < d || (od == d && ok < k)) { d = od; k = ok; }
        }
        if (tx == 0) s_idx[ty * 8 + i] = k;
    }
    __syncthreads();

    // Epilogue: straight-through z_q write (coalesced), loss partial, idx write
    float lsum = 0.0f;
    float* out_base = out_zq + (size_t)b * (DDIM * HW) + hw0;
    #pragma unroll 4
    for (int r = 0; r < 128; r++) {
        int e  = r * 256 + t;       // 32768 elements
        int c  = e >> 7;
        int px = e & 127;
        int kk = s_idx[px];
        float q  = __ldg(&cb[(size_t)kk * DDIM + c]);
        float zv = z_s[c * TILE_PX + px];
        float dd = __fsub_rn(q, zv);                 // z_q - z
        lsum = fmaf(dd, dd, lsum);                   // loss partial
        out_base[(size_t)c * HW + px] = __fadd_rn(zv, dd);  // z + (z_q - z)
    }
    if (t < 128) out_idx[(size_t)tile * TILE_PX + t] = (float)s_idx[t];

    // block loss reduce
    #pragma unroll
    for (int off = 16; off >= 1; off >>= 1)
        lsum += __shfl_xor_sync(0xFFFFFFFFu, lsum, off);
    if ((t & 31) == 0) swsum[t >> 5] = lsum;
    __syncthreads();
    if (t == 0) {
        float bs = 0.0f;
        #pragma unroll
        for (int w = 0; w < 8; w++) bs += swsum[w];
        atomicAdd(&g_loss_acc, bs);
    }
}

// ---------------------------------------------------------------------------
// Finalize: loss = mean + BETA*mean = 1.25 * (sum / 2^24)
// ---------------------------------------------------------------------------
__global__ void vq_finalize(float* __restrict__ out) {
    float m = __fmul_rn(g_loss_acc, 1.0f / (float)ZQ_ELEMS);  // /2^24 exact
    out[ZQ_ELEMS + NPX] = __fmul_rn(1.25f, m);
}

extern "C" void kernel_launch(void* const* d_in, const int* in_sizes, int n_in,
                              void* d_out, int out_size) {
    const float* z  = (const float*)d_in[0];
    const float* cb = (const float*)d_in[1];
    float* out = (float*)d_out;

    // out layout: [z_q: 16777216][idx: 65536][loss: 1]
    float* out_zq  = out;
    float* out_idx = out + ZQ_ELEMS;

    vq_prep<<<32, 32>>>(cb);

    size_t smem_bytes = SMEM_FLOATS * sizeof(float);
    cudaFuncSetAttribute(vq_main, cudaFuncAttributeMaxDynamicSharedMemorySize,
                         (int)smem_bytes);
    vq_main<<<NPX / TILE_PX, 256, smem_bytes>>>(z, cb, out_zq, out_idx);

    vq_finalize<<<1, 1>>>(out);
}